// round 10
// baseline (speedup 1.0000x reference)
#include <cuda_runtime.h>
#include <cuda_bf16.h>
#include <cstdint>

#define D 128
#define MAXN 50176        // padded node capacity (actual N = 50000)
#define MAXE 600000

// ---------------- scratch (no allocs allowed) ----------------
__device__ int   g_cnt[MAXN];
__device__ int   g_fill[MAXN];
__device__ int   g_row[MAXN + 1];
__device__ int   g_csrc[MAXE];
__device__ float g_inv[MAXN];
__device__ float g_hop1[MAXN * D];
__device__ float g_hop2[MAXN * D];

// ---------------- zero the small int arrays ----------------
__global__ void zero_kernel() {
    int i = blockIdx.x * blockDim.x + threadIdx.x;
    if (i < MAXN) { g_cnt[i] = 0; g_fill[i] = 0; }
}

// ---------------- in-degree histogram ----------------
__global__ void degree_kernel(const int* __restrict__ ei, int E) {
    int e = blockIdx.x * blockDim.x + threadIdx.x;
    if (e < E) atomicAdd(&g_cnt[ei[E + e]], 1);
}

// ---------------- exclusive prefix sum (single block) ----------------
__global__ void scan_kernel() {
    __shared__ int sh[1024];
    const int CH = MAXN / 1024;        // 49
    int t = threadIdx.x;
    int base = t * CH;

    int s = 0;
    for (int i = 0; i < CH; i++) s += g_cnt[base + i];
    sh[t] = s;
    __syncthreads();
    for (int off = 1; off < 1024; off <<= 1) {
        int v = (t >= off) ? sh[t - off] : 0;
        __syncthreads();
        sh[t] += v;
        __syncthreads();
    }
    int run = (t == 0) ? 0 : sh[t - 1];
    for (int i = 0; i < CH; i++) {
        int idx = base + i;
        int c = g_cnt[idx];
        g_row[idx] = run;
        g_inv[idx] = 1.0f / fmaxf((float)c, 1.0f);
        run += c;
    }
    if (t == 1023) g_row[MAXN] = run;
}

// ---------------- CSR fill ----------------
__global__ void fill_kernel(const int* __restrict__ ei, int E) {
    int e = blockIdx.x * blockDim.x + threadIdx.x;
    if (e < E) {
        int s = ei[e];
        int d = ei[E + e];
        int pos = g_row[d] + atomicAdd(&g_fill[d], 1);
        g_csrc[pos] = s;
    }
}

// ---------------- mean aggregation (pull): one warp per dst node ----------------
__global__ void hop_kernel(const float* __restrict__ x, int pass, int n) {
    int w = (blockIdx.x * blockDim.x + threadIdx.x) >> 5;
    if (w >= n) return;
    int lane = threadIdx.x & 31;

    const float4* in = (pass == 0) ? (const float4*)x : (const float4*)g_hop1;
    float*        op = (pass == 0) ? g_hop1 : g_hop2;

    int beg = g_row[w];
    int end = g_row[w + 1];

    float ax = 0.f, ay = 0.f, az = 0.f, aw = 0.f;
    int j = beg;
    for (; j + 4 <= end; j += 4) {
        int s0 = __ldg(&g_csrc[j + 0]);
        int s1 = __ldg(&g_csrc[j + 1]);
        int s2 = __ldg(&g_csrc[j + 2]);
        int s3 = __ldg(&g_csrc[j + 3]);
        float4 v0 = __ldg(in + (size_t)s0 * 32 + lane);
        float4 v1 = __ldg(in + (size_t)s1 * 32 + lane);
        float4 v2 = __ldg(in + (size_t)s2 * 32 + lane);
        float4 v3 = __ldg(in + (size_t)s3 * 32 + lane);
        ax += v0.x; ay += v0.y; az += v0.z; aw += v0.w;
        ax += v1.x; ay += v1.y; az += v1.z; aw += v1.w;
        ax += v2.x; ay += v2.y; az += v2.z; aw += v2.w;
        ax += v3.x; ay += v3.y; az += v3.z; aw += v3.w;
    }
    for (; j < end; j++) {
        int s0 = __ldg(&g_csrc[j]);
        float4 v0 = __ldg(in + (size_t)s0 * 32 + lane);
        ax += v0.x; ay += v0.y; az += v0.z; aw += v0.w;
    }
    float inv = g_inv[w];
    float4 r = make_float4(ax * inv, ay * inv, az * inv, aw * inv);
    *((float4*)op + (size_t)w * 32 + lane) = r;
}

// ---------------- bf16 split helpers ----------------
__device__ __forceinline__ void split2(float f0, float f1, uint32_t& hi, uint32_t& lo) {
    __nv_bfloat16 h0 = __float2bfloat16(f0);
    __nv_bfloat16 h1 = __float2bfloat16(f1);
    __nv_bfloat16 l0 = __float2bfloat16(f0 - __bfloat162float(h0));
    __nv_bfloat16 l1 = __float2bfloat16(f1 - __bfloat162float(h1));
    hi = (uint32_t)__bfloat16_as_ushort(h0) | ((uint32_t)__bfloat16_as_ushort(h1) << 16);
    lo = (uint32_t)__bfloat16_as_ushort(l0) | ((uint32_t)__bfloat16_as_ushort(l1) << 16);
}

__device__ __forceinline__ void mma_bf16(float* c, const uint32_t* a, const uint32_t* b) {
    asm volatile(
        "mma.sync.aligned.m16n8k16.row.col.f32.bf16.bf16.f32 "
        "{%0,%1,%2,%3}, {%4,%5,%6,%7}, {%8,%9}, {%0,%1,%2,%3};"
        : "+f"(c[0]), "+f"(c[1]), "+f"(c[2]), "+f"(c[3])
        : "r"(a[0]), "r"(a[1]), "r"(a[2]), "r"(a[3]), "r"(b[0]), "r"(b[1]));
}

// ---------------- HMMA split-bf16 partial GEMM ----------------
// out (+)= A @ W[:, koff:koff+128]^T  (+ bias if first).
// A selected by sel: 0=x, 1=g_hop1, 2=g_hop2. CTA 128x128, 8 warps, warp 32x64.
// 3 passes per k-step: Ahi*Bhi + Alo*Bhi + Ahi*Blo.
#define SSTR 40   // padded bf16 row stride (conflict-free fragment LDS)
__global__ __launch_bounds__(256, 2)
void hmma_gemm_kernel(const float* __restrict__ x,
                      const float* __restrict__ W,     // [128, 384]
                      const float* __restrict__ bias,  // [128]
                      float* __restrict__ out, int n,
                      int sel, int koff, int first) {
    __shared__ __nv_bfloat16 Ahi[128][SSTR], Alo[128][SSTR];
    __shared__ __nv_bfloat16 Bhi[128][SSTR], Blo[128][SSTR];

    int tid = threadIdx.x;
    int wid = tid >> 5, lane = tid & 31;
    int wm = wid & 3;            // warp row:   m in [wm*32, +32)
    int wn = wid >> 2;           // warp col:   o in [wn*64, +64)
    int g = lane >> 2, tig = lane & 3;
    int m0 = blockIdx.x * 128;

    const float* A = (sel == 0) ? x : (sel == 1) ? g_hop1 : g_hop2;

    float acc[2][8][4];
#pragma unroll
    for (int mt = 0; mt < 2; mt++)
#pragma unroll
        for (int nt = 0; nt < 8; nt++)
#pragma unroll
            for (int q = 0; q < 4; q++) acc[mt][nt][q] = 0.f;

    int lrow = tid >> 1;                 // loader row 0..127
    int lh   = (tid & 1) * 16;           // k half within 32-chunk
    bool avalid = (m0 + lrow) < n;

    float4 av[4], wv[4];
    auto load_tile = [&](int kt) {
        const float4* ap = (const float4*)(A + (size_t)(m0 + lrow) * 128 + kt * 32 + lh);
        const float4* wp = (const float4*)(W + (size_t)lrow * 384 + koff + kt * 32 + lh);
#pragma unroll
        for (int q = 0; q < 4; q++) {
            av[q] = avalid ? __ldg(ap + q) : make_float4(0.f, 0.f, 0.f, 0.f);
            wv[q] = __ldg(wp + q);
        }
    };
    load_tile(0);

#pragma unroll 1
    for (int kt = 0; kt < 4; kt++) {
        __syncthreads();   // previous tile fully consumed
#pragma unroll
        for (int q = 0; q < 4; q++) {
            uint32_t h0, l0, h1, l1;
            int kc = lh + q * 4;
            split2(av[q].x, av[q].y, h0, l0);
            split2(av[q].z, av[q].w, h1, l1);
            *(uint32_t*)&Ahi[lrow][kc]     = h0;
            *(uint32_t*)&Ahi[lrow][kc + 2] = h1;
            *(uint32_t*)&Alo[lrow][kc]     = l0;
            *(uint32_t*)&Alo[lrow][kc + 2] = l1;
            split2(wv[q].x, wv[q].y, h0, l0);
            split2(wv[q].z, wv[q].w, h1, l1);
            *(uint32_t*)&Bhi[lrow][kc]     = h0;
            *(uint32_t*)&Bhi[lrow][kc + 2] = h1;
            *(uint32_t*)&Blo[lrow][kc]     = l0;
            *(uint32_t*)&Blo[lrow][kc + 2] = l1;
        }
        __syncthreads();

        if (kt < 3) load_tile(kt + 1);   // prefetch: LDG hidden under MMA below

#pragma unroll
        for (int ks = 0; ks < 2; ks++) {
            int kb = ks * 16 + tig * 2;

            uint32_t afh[2][4], afl[4];
#pragma unroll
            for (int mt = 0; mt < 2; mt++) {
                int am = wm * 32 + mt * 16 + g;
                afh[mt][0] = *(const uint32_t*)&Ahi[am][kb];
                afh[mt][1] = *(const uint32_t*)&Ahi[am + 8][kb];
                afh[mt][2] = *(const uint32_t*)&Ahi[am][kb + 8];
                afh[mt][3] = *(const uint32_t*)&Ahi[am + 8][kb + 8];
            }

            uint32_t bf[8][2];
#pragma unroll
            for (int nt = 0; nt < 8; nt++) {
                int nn = wn * 64 + nt * 8 + g;
                bf[nt][0] = *(const uint32_t*)&Bhi[nn][kb];
                bf[nt][1] = *(const uint32_t*)&Bhi[nn][kb + 8];
            }
#pragma unroll
            for (int mt = 0; mt < 2; mt++) {
                int am = wm * 32 + mt * 16 + g;
                afl[0] = *(const uint32_t*)&Alo[am][kb];
                afl[1] = *(const uint32_t*)&Alo[am + 8][kb];
                afl[2] = *(const uint32_t*)&Alo[am][kb + 8];
                afl[3] = *(const uint32_t*)&Alo[am + 8][kb + 8];
#pragma unroll
                for (int nt = 0; nt < 8; nt++) {
                    mma_bf16(acc[mt][nt], afh[mt], bf[nt]);
                    mma_bf16(acc[mt][nt], afl, bf[nt]);
                }
            }
#pragma unroll
            for (int nt = 0; nt < 8; nt++) {
                int nn = wn * 64 + nt * 8 + g;
                bf[nt][0] = *(const uint32_t*)&Blo[nn][kb];
                bf[nt][1] = *(const uint32_t*)&Blo[nn][kb + 8];
            }
#pragma unroll
            for (int mt = 0; mt < 2; mt++)
#pragma unroll
                for (int nt = 0; nt < 8; nt++)
                    mma_bf16(acc[mt][nt], afh[mt], bf[nt]);
        }
    }

    // epilogue: out = acc + bias (first) or out += acc
#pragma unroll
    for (int mt = 0; mt < 2; mt++) {
        int row = m0 + wm * 32 + mt * 16 + g;
#pragma unroll
        for (int nt = 0; nt < 8; nt++) {
            int col = wn * 64 + nt * 8 + tig * 2;
            if (first) {
                float2 bb = *(const float2*)&bias[col];
                if (row < n) {
                    float2 r0 = make_float2(acc[mt][nt][0] + bb.x, acc[mt][nt][1] + bb.y);
                    *(float2*)&out[(size_t)row * 128 + col] = r0;
                }
                if (row + 8 < n) {
                    float2 r1 = make_float2(acc[mt][nt][2] + bb.x, acc[mt][nt][3] + bb.y);
                    *(float2*)&out[(size_t)(row + 8) * 128 + col] = r1;
                }
            } else {
                if (row < n) {
                    float2 o = *(float2*)&out[(size_t)row * 128 + col];
                    o.x += acc[mt][nt][0]; o.y += acc[mt][nt][1];
                    *(float2*)&out[(size_t)row * 128 + col] = o;
                }
                if (row + 8 < n) {
                    float2 o = *(float2*)&out[(size_t)(row + 8) * 128 + col];
                    o.x += acc[mt][nt][2]; o.y += acc[mt][nt][3];
                    *(float2*)&out[(size_t)(row + 8) * 128 + col] = o;
                }
            }
        }
    }
}

// ---------------- launch: fork-join overlap of GEMM stream with graph stream ----------------
extern "C" void kernel_launch(void* const* d_in, const int* in_sizes, int n_in,
                              void* d_out, int out_size) {
    const float* x    = (const float*)d_in[0];
    const int*   ei   = (const int*)d_in[1];      // int32 (JAX x64 disabled)
    const float* W    = (const float*)d_in[2];
    const float* bias = (const float*)d_in[3];
    float*       out  = (float*)d_out;

    int n = in_sizes[0] / D;      // 50000
    int E = in_sizes[1] / 2;      // 600000

    // one-time stream/event creation (resources only; enqueued work is identical every call)
    static cudaStream_t s2 = nullptr;
    static cudaEvent_t ev_root, ev_h1, ev_h2, ev_join;
    if (s2 == nullptr) {
        cudaStreamCreateWithFlags(&s2, cudaStreamNonBlocking);
        cudaEventCreateWithFlags(&ev_root, cudaEventDisableTiming);
        cudaEventCreateWithFlags(&ev_h1,   cudaEventDisableTiming);
        cudaEventCreateWithFlags(&ev_h2,   cudaEventDisableTiming);
        cudaEventCreateWithFlags(&ev_join, cudaEventDisableTiming);
    }

    int gemm_blocks = (n + 127) / 128;
    int hop_blocks  = (n * 32 + 255) / 256;

    // fork: GEMM over x depends only on inputs -> runs concurrent with CSR + hop1
    cudaEventRecord(ev_root, 0);
    cudaStreamWaitEvent(s2, ev_root, 0);
    hmma_gemm_kernel<<<gemm_blocks, 256, 0, s2>>>(x, W, bias, out, n, 0, 0, 1);

    // main stream: CSR build + hops
    zero_kernel<<<(MAXN + 255) / 256, 256>>>();
    degree_kernel<<<(E + 255) / 256, 256>>>(ei, E);
    scan_kernel<<<1, 1024>>>();
    fill_kernel<<<(E + 255) / 256, 256>>>(ei, E);

    hop_kernel<<<hop_blocks, 256>>>(x, 0, n);
    cudaEventRecord(ev_h1, 0);
    hop_kernel<<<hop_blocks, 256>>>(x, 1, n);
    cudaEventRecord(ev_h2, 0);

    // GEMM over hop1 (after hop1 and after gemm1 by stream order)
    cudaStreamWaitEvent(s2, ev_h1, 0);
    hmma_gemm_kernel<<<gemm_blocks, 256, 0, s2>>>(x, W, bias, out, n, 1, 128, 0);

    // GEMM over hop2 (critical path tail)
    cudaStreamWaitEvent(s2, ev_h2, 0);
    hmma_gemm_kernel<<<gemm_blocks, 256, 0, s2>>>(x, W, bias, out, n, 2, 256, 0);

    // join back to the captured/main stream
    cudaEventRecord(ev_join, s2);
    cudaStreamWaitEvent(0, ev_join, 0);
}

// round 11
// speedup vs baseline: 1.7224x; 1.7224x over previous
#include <cuda_runtime.h>
#include <cuda_bf16.h>
#include <cstdint>

#define D 128
#define MAXN 50176        // padded node capacity (actual N = 50000)
#define MAXE 600000
#define SCAN_BLK 512
#define NSCAN (MAXN / SCAN_BLK)   // 98

// ---------------- scratch (no allocs allowed) ----------------
__device__ int   g_cnt[MAXN];
__device__ int   g_fill[MAXN];
__device__ int   g_row[MAXN + 1];
__device__ int   g_bsum[NSCAN];
__device__ int   g_csrc[MAXE];
__device__ float g_inv[MAXN];
__device__ float g_hop1[MAXN * D];
__device__ float g_hop2[MAXN * D];

// ---------------- zero the small int arrays ----------------
__global__ void zero_kernel() {
    int i = blockIdx.x * blockDim.x + threadIdx.x;
    if (i < MAXN) { g_cnt[i] = 0; g_fill[i] = 0; }
}

// ---------------- in-degree histogram ----------------
__global__ void degree_kernel(const int* __restrict__ ei, int E) {
    int e = blockIdx.x * blockDim.x + threadIdx.x;
    if (e < E) atomicAdd(&g_cnt[ei[E + e]], 1);
}

// ---------------- two-level scan ----------------
// scan1: per-block exclusive prefix into g_row, block sum into g_bsum, g_inv.
__global__ void scan1_kernel() {
    __shared__ int sh[SCAN_BLK];
    int t = threadIdx.x;
    int i = blockIdx.x * SCAN_BLK + t;
    int v = g_cnt[i];
    sh[t] = v;
    __syncthreads();
#pragma unroll
    for (int off = 1; off < SCAN_BLK; off <<= 1) {
        int u = (t >= off) ? sh[t - off] : 0;
        __syncthreads();
        sh[t] += u;
        __syncthreads();
    }
    g_row[i] = sh[t] - v;                      // exclusive within block
    g_inv[i] = 1.0f / fmaxf((float)v, 1.0f);
    if (t == SCAN_BLK - 1) g_bsum[blockIdx.x] = sh[t];
}

// scan2: single small block scans the NSCAN block sums (exclusive).
__global__ void scan2_kernel() {
    __shared__ int sh[128];
    int t = threadIdx.x;                       // 128 threads, NSCAN=98 <= 128
    int v = (t < NSCAN) ? g_bsum[t] : 0;
    sh[t] = v;
    __syncthreads();
#pragma unroll
    for (int off = 1; off < 128; off <<= 1) {
        int u = (t >= off) ? sh[t - off] : 0;
        __syncthreads();
        sh[t] += u;
        __syncthreads();
    }
    if (t < NSCAN) g_bsum[t] = sh[t] - v;      // exclusive
}

// scan3: add block offsets.
__global__ void scan3_kernel() {
    int i = blockIdx.x * SCAN_BLK + threadIdx.x;
    g_row[i] += g_bsum[blockIdx.x];
}

// ---------------- CSR fill ----------------
__global__ void fill_kernel(const int* __restrict__ ei, int E) {
    int e = blockIdx.x * blockDim.x + threadIdx.x;
    if (e < E) {
        int s = ei[e];
        int d = ei[E + e];
        int pos = g_row[d] + atomicAdd(&g_fill[d], 1);
        g_csrc[pos] = s;
    }
}

// ---------------- mean aggregation (pull): one warp per dst node ----------------
__global__ void hop_kernel(const float* __restrict__ x, int pass, int n) {
    int w = (blockIdx.x * blockDim.x + threadIdx.x) >> 5;
    if (w >= n) return;
    int lane = threadIdx.x & 31;

    const float4* in = (pass == 0) ? (const float4*)x : (const float4*)g_hop1;
    float*        op = (pass == 0) ? g_hop1 : g_hop2;

    int beg = g_row[w];
    int end = g_row[w + 1];

    float ax = 0.f, ay = 0.f, az = 0.f, aw = 0.f;
    int j = beg;
    for (; j + 4 <= end; j += 4) {
        int s0 = __ldg(&g_csrc[j + 0]);
        int s1 = __ldg(&g_csrc[j + 1]);
        int s2 = __ldg(&g_csrc[j + 2]);
        int s3 = __ldg(&g_csrc[j + 3]);
        float4 v0 = __ldg(in + (size_t)s0 * 32 + lane);
        float4 v1 = __ldg(in + (size_t)s1 * 32 + lane);
        float4 v2 = __ldg(in + (size_t)s2 * 32 + lane);
        float4 v3 = __ldg(in + (size_t)s3 * 32 + lane);
        ax += v0.x; ay += v0.y; az += v0.z; aw += v0.w;
        ax += v1.x; ay += v1.y; az += v1.z; aw += v1.w;
        ax += v2.x; ay += v2.y; az += v2.z; aw += v2.w;
        ax += v3.x; ay += v3.y; az += v3.z; aw += v3.w;
    }
    for (; j < end; j++) {
        int s0 = __ldg(&g_csrc[j]);
        float4 v0 = __ldg(in + (size_t)s0 * 32 + lane);
        ax += v0.x; ay += v0.y; az += v0.z; aw += v0.w;
    }
    float inv = g_inv[w];
    float4 r = make_float4(ax * inv, ay * inv, az * inv, aw * inv);
    *((float4*)op + (size_t)w * 32 + lane) = r;
}

// ---------------- bf16 split helpers ----------------
__device__ __forceinline__ void split2(float f0, float f1, uint32_t& hi, uint32_t& lo) {
    __nv_bfloat16 h0 = __float2bfloat16(f0);
    __nv_bfloat16 h1 = __float2bfloat16(f1);
    __nv_bfloat16 l0 = __float2bfloat16(f0 - __bfloat162float(h0));
    __nv_bfloat16 l1 = __float2bfloat16(f1 - __bfloat162float(h1));
    hi = (uint32_t)__bfloat16_as_ushort(h0) | ((uint32_t)__bfloat16_as_ushort(h1) << 16);
    lo = (uint32_t)__bfloat16_as_ushort(l0) | ((uint32_t)__bfloat16_as_ushort(l1) << 16);
}

__device__ __forceinline__ void mma_bf16(float* c, const uint32_t* a, const uint32_t* b) {
    asm volatile(
        "mma.sync.aligned.m16n8k16.row.col.f32.bf16.bf16.f32 "
        "{%0,%1,%2,%3}, {%4,%5,%6,%7}, {%8,%9}, {%0,%1,%2,%3};"
        : "+f"(c[0]), "+f"(c[1]), "+f"(c[2]), "+f"(c[3])
        : "r"(a[0]), "r"(a[1]), "r"(a[2]), "r"(a[3]), "r"(b[0]), "r"(b[1]));
}

// ---------------- HMMA split-bf16 fused concat-GEMM (R9, proven) ----------------
// out = [x|hop1|hop2] @ W^T + b.  CTA: 128 nodes x 128 outs. 8 warps, warp 32x64.
// 3 passes per k-step: Ahi*Bhi + Alo*Bhi + Ahi*Blo (lo*lo dropped, ~2^-18).
#define SSTR 40   // padded bf16 row stride (conflict-free fragment LDS)
__global__ __launch_bounds__(256, 2)
void hmma_gemm_kernel(const float* __restrict__ x,
                      const float* __restrict__ W,     // [128, 384]
                      const float* __restrict__ bias,  // [128]
                      float* __restrict__ out, int n) {
    __shared__ __nv_bfloat16 Ahi[128][SSTR], Alo[128][SSTR];
    __shared__ __nv_bfloat16 Bhi[128][SSTR], Blo[128][SSTR];

    int tid = threadIdx.x;
    int wid = tid >> 5, lane = tid & 31;
    int wm = wid & 3;            // warp row:   m in [wm*32, +32)
    int wn = wid >> 2;           // warp col:   o in [wn*64, +64)
    int g = lane >> 2, tig = lane & 3;
    int m0 = blockIdx.x * 128;

    float acc[2][8][4];
#pragma unroll
    for (int mt = 0; mt < 2; mt++)
#pragma unroll
        for (int nt = 0; nt < 8; nt++)
#pragma unroll
            for (int q = 0; q < 4; q++) acc[mt][nt][q] = 0.f;

    int lrow = tid >> 1;                 // loader row 0..127
    int lh   = (tid & 1) * 16;           // k half within 32-chunk
    bool avalid = (m0 + lrow) < n;

#pragma unroll 1
    for (int kt = 0; kt < 12; kt++) {
        const float* A = (kt < 4) ? x : (kt < 8) ? g_hop1 : g_hop2;
        int ka = (kt & 3) * 32;

        float4 av[4], wv[4];
        const float4* ap = (const float4*)(A + (size_t)(m0 + lrow) * 128 + ka + lh);
        const float4* wp = (const float4*)(W + (size_t)lrow * 384 + kt * 32 + lh);
#pragma unroll
        for (int q = 0; q < 4; q++) {
            av[q] = avalid ? __ldg(ap + q) : make_float4(0.f, 0.f, 0.f, 0.f);
            wv[q] = __ldg(wp + q);
        }

        __syncthreads();   // previous tile fully consumed
#pragma unroll
        for (int q = 0; q < 4; q++) {
            uint32_t h0, l0, h1, l1;
            int kc = lh + q * 4;
            split2(av[q].x, av[q].y, h0, l0);
            split2(av[q].z, av[q].w, h1, l1);
            *(uint32_t*)&Ahi[lrow][kc]     = h0;
            *(uint32_t*)&Ahi[lrow][kc + 2] = h1;
            *(uint32_t*)&Alo[lrow][kc]     = l0;
            *(uint32_t*)&Alo[lrow][kc + 2] = l1;
            split2(wv[q].x, wv[q].y, h0, l0);
            split2(wv[q].z, wv[q].w, h1, l1);
            *(uint32_t*)&Bhi[lrow][kc]     = h0;
            *(uint32_t*)&Bhi[lrow][kc + 2] = h1;
            *(uint32_t*)&Blo[lrow][kc]     = l0;
            *(uint32_t*)&Blo[lrow][kc + 2] = l1;
        }
        __syncthreads();

#pragma unroll
        for (int ks = 0; ks < 2; ks++) {
            int kb = ks * 16 + tig * 2;

            uint32_t afh[2][4], afl[4];
#pragma unroll
            for (int mt = 0; mt < 2; mt++) {
                int am = wm * 32 + mt * 16 + g;
                afh[mt][0] = *(const uint32_t*)&Ahi[am][kb];
                afh[mt][1] = *(const uint32_t*)&Ahi[am + 8][kb];
                afh[mt][2] = *(const uint32_t*)&Ahi[am][kb + 8];
                afh[mt][3] = *(const uint32_t*)&Ahi[am + 8][kb + 8];
            }

            uint32_t bf[8][2];
#pragma unroll
            for (int nt = 0; nt < 8; nt++) {
                int nn = wn * 64 + nt * 8 + g;
                bf[nt][0] = *(const uint32_t*)&Bhi[nn][kb];
                bf[nt][1] = *(const uint32_t*)&Bhi[nn][kb + 8];
            }
#pragma unroll
            for (int mt = 0; mt < 2; mt++) {
                int am = wm * 32 + mt * 16 + g;
                afl[0] = *(const uint32_t*)&Alo[am][kb];
                afl[1] = *(const uint32_t*)&Alo[am + 8][kb];
                afl[2] = *(const uint32_t*)&Alo[am][kb + 8];
                afl[3] = *(const uint32_t*)&Alo[am + 8][kb + 8];
#pragma unroll
                for (int nt = 0; nt < 8; nt++) {
                    mma_bf16(acc[mt][nt], afh[mt], bf[nt]);
                    mma_bf16(acc[mt][nt], afl, bf[nt]);
                }
            }
#pragma unroll
            for (int nt = 0; nt < 8; nt++) {
                int nn = wn * 64 + nt * 8 + g;
                bf[nt][0] = *(const uint32_t*)&Blo[nn][kb];
                bf[nt][1] = *(const uint32_t*)&Blo[nn][kb + 8];
            }
#pragma unroll
            for (int mt = 0; mt < 2; mt++)
#pragma unroll
                for (int nt = 0; nt < 8; nt++)
                    mma_bf16(acc[mt][nt], afh[mt], bf[nt]);
        }
    }

    // epilogue: acc -> out (+bias)
#pragma unroll
    for (int mt = 0; mt < 2; mt++) {
        int row = m0 + wm * 32 + mt * 16 + g;
#pragma unroll
        for (int nt = 0; nt < 8; nt++) {
            int col = wn * 64 + nt * 8 + tig * 2;
            float2 bb = *(const float2*)&bias[col];
            if (row < n) {
                float2 r0 = make_float2(acc[mt][nt][0] + bb.x, acc[mt][nt][1] + bb.y);
                *(float2*)&out[(size_t)row * 128 + col] = r0;
            }
            if (row + 8 < n) {
                float2 r1 = make_float2(acc[mt][nt][2] + bb.x, acc[mt][nt][3] + bb.y);
                *(float2*)&out[(size_t)(row + 8) * 128 + col] = r1;
            }
        }
    }
}

// ---------------- launch (single stream, R9 structure + parallel scan) ----------------
extern "C" void kernel_launch(void* const* d_in, const int* in_sizes, int n_in,
                              void* d_out, int out_size) {
    const float* x    = (const float*)d_in[0];
    const int*   ei   = (const int*)d_in[1];      // int32 (JAX x64 disabled)
    const float* W    = (const float*)d_in[2];
    const float* bias = (const float*)d_in[3];
    float*       out  = (float*)d_out;

    int n = in_sizes[0] / D;      // 50000
    int E = in_sizes[1] / 2;      // 600000

    // CSR build (by destination), two-level parallel scan
    zero_kernel<<<(MAXN + 255) / 256, 256>>>();
    degree_kernel<<<(E + 255) / 256, 256>>>(ei, E);
    scan1_kernel<<<NSCAN, SCAN_BLK>>>();
    scan2_kernel<<<1, 128>>>();
    scan3_kernel<<<NSCAN, SCAN_BLK>>>();
    fill_kernel<<<(E + 255) / 256, 256>>>(ei, E);

    // two mean-propagation hops
    int hop_blocks = (n * 32 + 255) / 256;
    hop_kernel<<<hop_blocks, 256>>>(x, 0, n);
    hop_kernel<<<hop_blocks, 256>>>(x, 1, n);

    // split-bf16 HMMA GEMM
    hmma_gemm_kernel<<<(n + 127) / 128, 256>>>(x, W, bias, out, n);
}

// round 12
// speedup vs baseline: 1.7228x; 1.0002x over previous
#include <cuda_runtime.h>
#include <cuda_bf16.h>
#include <cstdint>

#define D 128
#define MAXN 50176        // padded node capacity (actual N = 50000)
#define MAXE 600000
#define SCAN_BLK 512
#define NSCAN (MAXN / SCAN_BLK)   // 98

// ---------------- scratch (no allocs allowed) ----------------
__device__ int   g_cnt[MAXN];          // zero at start of every call (self-restoring)
__device__ int   g_fill[MAXN];         // set by scan3 to row start each call
__device__ int   g_row[MAXN + 1];
__device__ int   g_bsum[NSCAN];
__device__ int   g_csrc[MAXE];
__device__ float g_inv[MAXN];
__device__ float g_hop1[MAXN * D];
__device__ float g_hop2[MAXN * D];

// ---------------- in-degree histogram (2 edges/thread) ----------------
__global__ void degree_kernel(const int* __restrict__ ei, int E) {
    int i = blockIdx.x * blockDim.x + threadIdx.x;
    if (i < E / 2) {
        int2 d2 = ((const int2*)(ei + E))[i];
        atomicAdd(&g_cnt[d2.x], 1);
        atomicAdd(&g_cnt[d2.y], 1);
    }
}

// ---------------- scan1: per-block exclusive prefix, block sum, inv-degree ----------------
// Also zeroes g_cnt in place so the next call starts clean (no zero_kernel).
__global__ void scan1_kernel() {
    __shared__ int sh[SCAN_BLK];
    int t = threadIdx.x;
    int i = blockIdx.x * SCAN_BLK + t;
    int v = g_cnt[i];
    g_cnt[i] = 0;                              // self-restore for next replay
    sh[t] = v;
    __syncthreads();
#pragma unroll
    for (int off = 1; off < SCAN_BLK; off <<= 1) {
        int u = (t >= off) ? sh[t - off] : 0;
        __syncthreads();
        sh[t] += u;
        __syncthreads();
    }
    g_row[i] = sh[t] - v;                      // exclusive within block
    g_inv[i] = 1.0f / fmaxf((float)v, 1.0f);
    if (t == SCAN_BLK - 1) g_bsum[blockIdx.x] = sh[t];
}

// ---------------- scan3: add block offsets (redundant per-block scan of bsum) ----------------
// Writes final offsets into BOTH g_row and g_fill (fill cursor starts at row start).
__global__ void scan3_kernel() {
    __shared__ int sh[128];
    int t = threadIdx.x;
    if (t < 128) sh[t] = (t < NSCAN) ? g_bsum[t] : 0;
    __syncthreads();
#pragma unroll
    for (int off = 1; off < 128; off <<= 1) {
        int u = (t < 128 && t >= off) ? sh[t - off] : 0;
        __syncthreads();
        if (t < 128) sh[t] += u;
        __syncthreads();
    }
    int offset = (blockIdx.x == 0) ? 0 : sh[blockIdx.x - 1];
    int i = blockIdx.x * SCAN_BLK + t;
    int r = g_row[i] + offset;
    g_row[i] = r;
    g_fill[i] = r;
}

// ---------------- CSR fill: cursor IS the position ----------------
__global__ void fill_kernel(const int* __restrict__ ei, int E) {
    int i = blockIdx.x * blockDim.x + threadIdx.x;
    if (i < E / 2) {
        int2 s2 = ((const int2*)ei)[i];
        int2 d2 = ((const int2*)(ei + E))[i];
        int p0 = atomicAdd(&g_fill[d2.x], 1);
        g_csrc[p0] = s2.x;
        int p1 = atomicAdd(&g_fill[d2.y], 1);
        g_csrc[p1] = s2.y;
    }
}

// ---------------- mean aggregation (pull): one warp per dst node ----------------
__global__ void hop_kernel(const float* __restrict__ x, int pass, int n) {
    int w = (blockIdx.x * blockDim.x + threadIdx.x) >> 5;
    if (w >= n) return;
    int lane = threadIdx.x & 31;

    const float4* in = (pass == 0) ? (const float4*)x : (const float4*)g_hop1;
    float*        op = (pass == 0) ? g_hop1 : g_hop2;

    int beg = g_row[w];
    int end = g_row[w + 1];

    float ax = 0.f, ay = 0.f, az = 0.f, aw = 0.f;
    int j = beg;
    for (; j + 4 <= end; j += 4) {
        int s0 = __ldg(&g_csrc[j + 0]);
        int s1 = __ldg(&g_csrc[j + 1]);
        int s2 = __ldg(&g_csrc[j + 2]);
        int s3 = __ldg(&g_csrc[j + 3]);
        float4 v0 = __ldg(in + (size_t)s0 * 32 + lane);
        float4 v1 = __ldg(in + (size_t)s1 * 32 + lane);
        float4 v2 = __ldg(in + (size_t)s2 * 32 + lane);
        float4 v3 = __ldg(in + (size_t)s3 * 32 + lane);
        ax += v0.x; ay += v0.y; az += v0.z; aw += v0.w;
        ax += v1.x; ay += v1.y; az += v1.z; aw += v1.w;
        ax += v2.x; ay += v2.y; az += v2.z; aw += v2.w;
        ax += v3.x; ay += v3.y; az += v3.z; aw += v3.w;
    }
    for (; j < end; j++) {
        int s0 = __ldg(&g_csrc[j]);
        float4 v0 = __ldg(in + (size_t)s0 * 32 + lane);
        ax += v0.x; ay += v0.y; az += v0.z; aw += v0.w;
    }
    float inv = g_inv[w];
    float4 r = make_float4(ax * inv, ay * inv, az * inv, aw * inv);
    *((float4*)op + (size_t)w * 32 + lane) = r;
}

// ---------------- bf16 split helpers ----------------
__device__ __forceinline__ void split2(float f0, float f1, uint32_t& hi, uint32_t& lo) {
    __nv_bfloat16 h0 = __float2bfloat16(f0);
    __nv_bfloat16 h1 = __float2bfloat16(f1);
    __nv_bfloat16 l0 = __float2bfloat16(f0 - __bfloat162float(h0));
    __nv_bfloat16 l1 = __float2bfloat16(f1 - __bfloat162float(h1));
    hi = (uint32_t)__bfloat16_as_ushort(h0) | ((uint32_t)__bfloat16_as_ushort(h1) << 16);
    lo = (uint32_t)__bfloat16_as_ushort(l0) | ((uint32_t)__bfloat16_as_ushort(l1) << 16);
}

__device__ __forceinline__ void mma_bf16(float* c, const uint32_t* a, const uint32_t* b) {
    asm volatile(
        "mma.sync.aligned.m16n8k16.row.col.f32.bf16.bf16.f32 "
        "{%0,%1,%2,%3}, {%4,%5,%6,%7}, {%8,%9}, {%0,%1,%2,%3};"
        : "+f"(c[0]), "+f"(c[1]), "+f"(c[2]), "+f"(c[3])
        : "r"(a[0]), "r"(a[1]), "r"(a[2]), "r"(a[3]), "r"(b[0]), "r"(b[1]));
}

// ---------------- HMMA split-bf16 fused concat-GEMM (proven R9) ----------------
#define SSTR 40   // padded bf16 row stride (conflict-free fragment LDS)
__global__ __launch_bounds__(256, 2)
void hmma_gemm_kernel(const float* __restrict__ x,
                      const float* __restrict__ W,     // [128, 384]
                      const float* __restrict__ bias,  // [128]
                      float* __restrict__ out, int n) {
    __shared__ __nv_bfloat16 Ahi[128][SSTR], Alo[128][SSTR];
    __shared__ __nv_bfloat16 Bhi[128][SSTR], Blo[128][SSTR];

    int tid = threadIdx.x;
    int wid = tid >> 5, lane = tid & 31;
    int wm = wid & 3;            // warp row:   m in [wm*32, +32)
    int wn = wid >> 2;           // warp col:   o in [wn*64, +64)
    int g = lane >> 2, tig = lane & 3;
    int m0 = blockIdx.x * 128;

    float acc[2][8][4];
#pragma unroll
    for (int mt = 0; mt < 2; mt++)
#pragma unroll
        for (int nt = 0; nt < 8; nt++)
#pragma unroll
            for (int q = 0; q < 4; q++) acc[mt][nt][q] = 0.f;

    int lrow = tid >> 1;                 // loader row 0..127
    int lh   = (tid & 1) * 16;           // k half within 32-chunk
    bool avalid = (m0 + lrow) < n;

#pragma unroll 1
    for (int kt = 0; kt < 12; kt++) {
        const float* A = (kt < 4) ? x : (kt < 8) ? g_hop1 : g_hop2;
        int ka = (kt & 3) * 32;

        float4 av[4], wv[4];
        const float4* ap = (const float4*)(A + (size_t)(m0 + lrow) * 128 + ka + lh);
        const float4* wp = (const float4*)(W + (size_t)lrow * 384 + kt * 32 + lh);
#pragma unroll
        for (int q = 0; q < 4; q++) {
            av[q] = avalid ? __ldg(ap + q) : make_float4(0.f, 0.f, 0.f, 0.f);
            wv[q] = __ldg(wp + q);
        }

        __syncthreads();   // previous tile fully consumed
#pragma unroll
        for (int q = 0; q < 4; q++) {
            uint32_t h0, l0, h1, l1;
            int kc = lh + q * 4;
            split2(av[q].x, av[q].y, h0, l0);
            split2(av[q].z, av[q].w, h1, l1);
            *(uint32_t*)&Ahi[lrow][kc]     = h0;
            *(uint32_t*)&Ahi[lrow][kc + 2] = h1;
            *(uint32_t*)&Alo[lrow][kc]     = l0;
            *(uint32_t*)&Alo[lrow][kc + 2] = l1;
            split2(wv[q].x, wv[q].y, h0, l0);
            split2(wv[q].z, wv[q].w, h1, l1);
            *(uint32_t*)&Bhi[lrow][kc]     = h0;
            *(uint32_t*)&Bhi[lrow][kc + 2] = h1;
            *(uint32_t*)&Blo[lrow][kc]     = l0;
            *(uint32_t*)&Blo[lrow][kc + 2] = l1;
        }
        __syncthreads();

#pragma unroll
        for (int ks = 0; ks < 2; ks++) {
            int kb = ks * 16 + tig * 2;

            uint32_t afh[2][4], afl[4];
#pragma unroll
            for (int mt = 0; mt < 2; mt++) {
                int am = wm * 32 + mt * 16 + g;
                afh[mt][0] = *(const uint32_t*)&Ahi[am][kb];
                afh[mt][1] = *(const uint32_t*)&Ahi[am + 8][kb];
                afh[mt][2] = *(const uint32_t*)&Ahi[am][kb + 8];
                afh[mt][3] = *(const uint32_t*)&Ahi[am + 8][kb + 8];
            }

            uint32_t bf[8][2];
#pragma unroll
            for (int nt = 0; nt < 8; nt++) {
                int nn = wn * 64 + nt * 8 + g;
                bf[nt][0] = *(const uint32_t*)&Bhi[nn][kb];
                bf[nt][1] = *(const uint32_t*)&Bhi[nn][kb + 8];
            }
#pragma unroll
            for (int mt = 0; mt < 2; mt++) {
                int am = wm * 32 + mt * 16 + g;
                afl[0] = *(const uint32_t*)&Alo[am][kb];
                afl[1] = *(const uint32_t*)&Alo[am + 8][kb];
                afl[2] = *(const uint32_t*)&Alo[am][kb + 8];
                afl[3] = *(const uint32_t*)&Alo[am + 8][kb + 8];
#pragma unroll
                for (int nt = 0; nt < 8; nt++) {
                    mma_bf16(acc[mt][nt], afh[mt], bf[nt]);
                    mma_bf16(acc[mt][nt], afl, bf[nt]);
                }
            }
#pragma unroll
            for (int nt = 0; nt < 8; nt++) {
                int nn = wn * 64 + nt * 8 + g;
                bf[nt][0] = *(const uint32_t*)&Blo[nn][kb];
                bf[nt][1] = *(const uint32_t*)&Blo[nn][kb + 8];
            }
#pragma unroll
            for (int mt = 0; mt < 2; mt++)
#pragma unroll
                for (int nt = 0; nt < 8; nt++)
                    mma_bf16(acc[mt][nt], afh[mt], bf[nt]);
        }
    }

    // epilogue: acc -> out (+bias)
#pragma unroll
    for (int mt = 0; mt < 2; mt++) {
        int row = m0 + wm * 32 + mt * 16 + g;
#pragma unroll
        for (int nt = 0; nt < 8; nt++) {
            int col = wn * 64 + nt * 8 + tig * 2;
            float2 bb = *(const float2*)&bias[col];
            if (row < n) {
                float2 r0 = make_float2(acc[mt][nt][0] + bb.x, acc[mt][nt][1] + bb.y);
                *(float2*)&out[(size_t)row * 128 + col] = r0;
            }
            if (row + 8 < n) {
                float2 r1 = make_float2(acc[mt][nt][2] + bb.x, acc[mt][nt][3] + bb.y);
                *(float2*)&out[(size_t)(row + 8) * 128 + col] = r1;
            }
        }
    }
}

// ---------------- launch (7 kernels, single stream) ----------------
extern "C" void kernel_launch(void* const* d_in, const int* in_sizes, int n_in,
                              void* d_out, int out_size) {
    const float* x    = (const float*)d_in[0];
    const int*   ei   = (const int*)d_in[1];      // int32 (JAX x64 disabled)
    const float* W    = (const float*)d_in[2];
    const float* bias = (const float*)d_in[3];
    float*       out  = (float*)d_out;

    int n = in_sizes[0] / D;      // 50000
    int E = in_sizes[1] / 2;      // 600000

    // CSR build (by destination)
    degree_kernel<<<(E / 2 + 255) / 256, 256>>>(ei, E);
    scan1_kernel<<<NSCAN, SCAN_BLK>>>();
    scan3_kernel<<<NSCAN, SCAN_BLK>>>();
    fill_kernel<<<(E / 2 + 255) / 256, 256>>>(ei, E);

    // two mean-propagation hops
    int hop_blocks = (n * 32 + 255) / 256;
    hop_kernel<<<hop_blocks, 256>>>(x, 0, n);
    hop_kernel<<<hop_blocks, 256>>>(x, 1, n);

    // split-bf16 HMMA GEMM
    hmma_gemm_kernel<<<(n + 127) / 128, 256>>>(x, W, bias, out, n);
}